// round 1
// baseline (speedup 1.0000x reference)
#include <cuda_runtime.h>

#define NB    8
#define IC    512
#define OC    512
#define PX    4096          // 64*64
#define KTOT  4608          // IC*9
#define BKC   8
#define NK    576           // KTOT/BKC

__device__ float g_smod[NB * IC];   // s[b][i] * C_CONV
__device__ float g_s2[NB * IC];     // s[b][i]^2
__device__ float g_sig[NB * OC];    // sigma_inv[b][o]

__device__ __forceinline__ unsigned long long pk2(float x, float y) {
    unsigned long long r;
    asm("mov.b64 %0, {%1, %2};" : "=l"(r) : "f"(x), "f"(y));
    return r;
}
__device__ __forceinline__ void upk2(unsigned long long v, float& x, float& y) {
    asm("mov.b64 {%0, %1}, %2;" : "=f"(x), "=f"(y) : "l"(v));
}
__device__ __forceinline__ void fma2(unsigned long long& d, unsigned long long a,
                                     unsigned long long b) {
    asm("fma.rn.f32x2 %0, %1, %2, %3;" : "=l"(d) : "l"(a), "l"(b), "l"(d));
}

// ---------------------------------------------------------------------------
// K1: s[b,i] = latent[b] . w_lin[i] * C_LIN + b_lin[i]
// ---------------------------------------------------------------------------
__global__ void k_style(const float* __restrict__ latent,
                        const float* __restrict__ w_lin,
                        const float* __restrict__ b_lin) {
    __shared__ float lat[512];
    const int b = blockIdx.x;
    const int i = threadIdx.x;
    lat[i] = latent[b * 512 + i];
    __syncthreads();
    const float* wr = w_lin + i * 512;
    float acc = 0.f;
#pragma unroll 8
    for (int l = 0; l < 512; ++l) acc += wr[l] * lat[l];
    const float C_LIN  = 0.04419417382415922f;   // 1/sqrt(512)
    const float C_CONV = 0.014731391274719742f;  // 1/sqrt(4608)
    float s = acc * C_LIN + b_lin[i];
    g_smod[b * 512 + i] = s * C_CONV;
    g_s2[b * 512 + i]   = s * s;
}

// ---------------------------------------------------------------------------
// K2: sigma_inv[b,o] = rsqrt( C_CONV^2 * sum_i (sum_t w_conv[o,i,t]^2) * s2[b,i] + eps )
// ---------------------------------------------------------------------------
__global__ void k_sigma(const float* __restrict__ w_conv) {
    __shared__ float red[8][128];
    const int o = blockIdx.x;
    const int tid = threadIdx.x;
    float acc[8];
#pragma unroll
    for (int b = 0; b < 8; ++b) acc[b] = 0.f;
    for (int i = tid; i < 512; i += 128) {
        const float* wp = w_conv + (o * 512 + i) * 9;
        float ws = 0.f;
#pragma unroll
        for (int t = 0; t < 9; ++t) { float v = wp[t]; ws += v * v; }
#pragma unroll
        for (int b = 0; b < 8; ++b) acc[b] += ws * g_s2[b * 512 + i];
    }
#pragma unroll
    for (int b = 0; b < 8; ++b) red[b][tid] = acc[b];
    __syncthreads();
    for (int st = 64; st > 0; st >>= 1) {
        if (tid < st) {
#pragma unroll
            for (int b = 0; b < 8; ++b) red[b][tid] += red[b][tid + st];
        }
        __syncthreads();
    }
    if (tid < 8) {
        const float C2 = 1.0f / 4608.0f;
        g_sig[tid * 512 + o] = rsqrtf(red[tid][0] * C2 + 1e-8f);
    }
}

// ---------------------------------------------------------------------------
// K3: implicit-GEMM conv. Per batch b: Y[o,p] = sum_k A[o,k] * B[k,p]
//   A[o,k] = w_conv[o, i(k), t(k)] * C_CONV * s[b, i(k)]   (modulation folded in)
//   B[k,p] = x[b, i(k), h(p)+dy(k), w(p)+dx(k)]            (implicit im2col)
// Tile: BM=128 (o), BN=128 (pixels), BK=8; 256 threads, 8x8 per thread,
// accumulation in packed f32x2 (2 pixels per FFMA2) for the dual-rate FP32 pipe.
// ---------------------------------------------------------------------------
__global__ void __launch_bounds__(256)
k_conv(const float* __restrict__ x, const float* __restrict__ w_conv,
       const float* __restrict__ b_conv, float* __restrict__ out) {
    __shared__ float As[2][8][132];
    __shared__ float Bs[2][8][132];

    const int b   = blockIdx.z;
    const int o0  = blockIdx.y << 7;
    const int p0  = blockIdx.x << 7;
    const int tid = threadIdx.x;
    const int tx  = tid & 15;
    const int ty  = tid >> 4;

    const float* __restrict__ xb   = x + b * (IC * PX);
    const float* __restrict__ smod = g_smod + b * IC;

    // A-tile load mapping: 128 o-rows x 8 k, 4 consecutive k per thread (float4)
    const int a_o  = tid >> 1;
    const int a_kb = (tid & 1) << 2;
    const float* wp = w_conv + (o0 + a_o) * KTOT + a_kb;

    // B-tile load mapping: 8 k-rows x 128 pixels, 4 consecutive pixels per thread
    const int b_kr = tid >> 5;
    const int b_pb = (tid & 31) << 2;

    unsigned long long acc[8][4];
#pragma unroll
    for (int i = 0; i < 8; ++i)
#pragma unroll
        for (int j = 0; j < 4; ++j) acc[i][j] = 0ull;

    auto loadA = [&](int k0, int buf) {
        float4 wv = *reinterpret_cast<const float4*>(wp + k0);
#pragma unroll
        for (int j = 0; j < 4; ++j) {
            int k = k0 + a_kb + j;
            unsigned ci = (unsigned)k / 9u;
            As[buf][a_kb + j][a_o] = (&wv.x)[j] * smod[ci];
        }
    };
    auto loadB = [&](int k0, int buf) {
        int k = k0 + b_kr;
        unsigned ci = (unsigned)k / 9u;
        int t  = k - (int)ci * 9;
        int dy = t / 3 - 1;
        int dx = t - (t / 3) * 3 - 1;
        const float* xc = xb + ci * PX;
#pragma unroll
        for (int j = 0; j < 4; ++j) {
            int p = p0 + b_pb + j;
            int h = (p >> 6) + dy;
            int w = (p & 63) + dx;
            float v = 0.f;
            if ((unsigned)h < 64u && (unsigned)w < 64u)
                v = __ldg(xc + (h << 6) + w);
            Bs[buf][b_kr][b_pb + j] = v;
        }
    };

    loadA(0, 0);
    loadB(0, 0);
    __syncthreads();

#pragma unroll 1
    for (int kt = 0; kt < NK; ++kt) {
        const int buf = kt & 1;
        if (kt + 1 < NK) {
            loadA((kt + 1) * BKC, buf ^ 1);
            loadB((kt + 1) * BKC, buf ^ 1);
        }
#pragma unroll
        for (int kk = 0; kk < 8; ++kk) {
            float4 a0 = *reinterpret_cast<const float4*>(&As[buf][kk][ty << 2]);
            float4 a1 = *reinterpret_cast<const float4*>(&As[buf][kk][64 + (ty << 2)]);
            ulonglong2 bq0 = *reinterpret_cast<const ulonglong2*>(&Bs[buf][kk][tx << 2]);
            ulonglong2 bq1 = *reinterpret_cast<const ulonglong2*>(&Bs[buf][kk][64 + (tx << 2)]);
            float av[8] = {a0.x, a0.y, a0.z, a0.w, a1.x, a1.y, a1.z, a1.w};
            unsigned long long bp[4] = {bq0.x, bq0.y, bq1.x, bq1.y};
#pragma unroll
            for (int i = 0; i < 8; ++i) {
                unsigned long long ai = pk2(av[i], av[i]);
#pragma unroll
                for (int j = 0; j < 4; ++j) fma2(acc[i][j], ai, bp[j]);
            }
        }
        __syncthreads();
    }

    // Epilogue: demodulate + bias, vectorized stores
#pragma unroll
    for (int i = 0; i < 8; ++i) {
        int o = o0 + ((i < 4) ? ((ty << 2) + i) : (64 + (ty << 2) + i - 4));
        float sg = g_sig[b * OC + o];
        float bc = b_conv[o];
        float* yr = out + ((long)(b * OC + o) << 12) + p0;
        float r[8];
#pragma unroll
        for (int j = 0; j < 4; ++j) {
            float lo, hi;
            upk2(acc[i][j], lo, hi);
            r[j * 2] = lo;
            r[j * 2 + 1] = hi;
        }
        float4 v0 = make_float4(r[0] * sg + bc, r[1] * sg + bc,
                                r[2] * sg + bc, r[3] * sg + bc);
        float4 v1 = make_float4(r[4] * sg + bc, r[5] * sg + bc,
                                r[6] * sg + bc, r[7] * sg + bc);
        *reinterpret_cast<float4*>(yr + (tx << 2)) = v0;
        *reinterpret_cast<float4*>(yr + 64 + (tx << 2)) = v1;
    }
}

// ---------------------------------------------------------------------------
extern "C" void kernel_launch(void* const* d_in, const int* in_sizes, int n_in,
                              void* d_out, int out_size) {
    const float* x      = (const float*)d_in[0];
    const float* latent = (const float*)d_in[1];
    const float* w_lin  = (const float*)d_in[2];
    const float* b_lin  = (const float*)d_in[3];
    const float* w_conv = (const float*)d_in[4];
    const float* b_conv = (const float*)d_in[5];
    float* out = (float*)d_out;

    k_style<<<NB, 512>>>(latent, w_lin, b_lin);
    k_sigma<<<OC, 128>>>(w_conv);
    k_conv<<<dim3(PX / 128, OC / 128, NB), 256>>>(x, w_conv, b_conv, out);
}

// round 3
// speedup vs baseline: 1.9644x; 1.9644x over previous
#include <cuda_runtime.h>
#include <cuda_bf16.h>
#include <cstdint>

#define NB   8
#define IC   512
#define OC   512
#define PX   4096
#define KTOT 4608
#define NKS  288           // KTOT / 16
#define STAGES 4

// ---------------- scratch (device globals; no allocation) ----------------
__device__ float g_smod[NB * IC];
__device__ float g_s2[NB * IC];
__device__ float g_sig[NB * OC];
__device__ __nv_bfloat16 g_Ahi[(size_t)NB * OC * KTOT];     // [b][o][k]
__device__ __nv_bfloat16 g_Alo[(size_t)NB * OC * KTOT];
__device__ __nv_bfloat16 g_Bhi[(size_t)NB * KTOT * PX];     // [b][k][p]
__device__ __nv_bfloat16 g_Blo[(size_t)NB * KTOT * PX];

// ---------------- baseline-PTX helpers (valid on plain sm_103) ----------------
__device__ __forceinline__ void cp16(uint32_t dst, const void* src) {
    asm volatile("cp.async.cg.shared.global [%0], [%1], 16;" :: "r"(dst), "l"(src));
}
__device__ __forceinline__ void cp_commit() {
    asm volatile("cp.async.commit_group;" ::: "memory");
}
__device__ __forceinline__ void cp_wait3() {
    asm volatile("cp.async.wait_group 3;" ::: "memory");
}
__device__ __forceinline__ void ldsm4(uint32_t* r, uint32_t a) {
    asm volatile("ldmatrix.sync.aligned.m8n8.x4.shared.b16 {%0,%1,%2,%3}, [%4];"
                 : "=r"(r[0]), "=r"(r[1]), "=r"(r[2]), "=r"(r[3]) : "r"(a));
}
__device__ __forceinline__ void ldsm4t(uint32_t* r, uint32_t a) {
    asm volatile("ldmatrix.sync.aligned.m8n8.x4.trans.shared.b16 {%0,%1,%2,%3}, [%4];"
                 : "=r"(r[0]), "=r"(r[1]), "=r"(r[2]), "=r"(r[3]) : "r"(a));
}
__device__ __forceinline__ void mma16816(float* c, const uint32_t* a, const uint32_t* b) {
    asm volatile(
        "mma.sync.aligned.m16n8k16.row.col.f32.bf16.bf16.f32 "
        "{%0,%1,%2,%3},{%4,%5,%6,%7},{%8,%9},{%0,%1,%2,%3};"
        : "+f"(c[0]), "+f"(c[1]), "+f"(c[2]), "+f"(c[3])
        : "r"(a[0]), "r"(a[1]), "r"(a[2]), "r"(a[3]), "r"(b[0]), "r"(b[1]));
}

// ---------------------------------------------------------------------------
// K1: style  s[b,i] = latent.w_lin * C_LIN + b_lin
// ---------------------------------------------------------------------------
__global__ void k_style(const float* __restrict__ latent,
                        const float* __restrict__ w_lin,
                        const float* __restrict__ b_lin) {
    __shared__ float lat[512];
    const int b = blockIdx.x;
    const int i = threadIdx.x;
    lat[i] = latent[b * 512 + i];
    __syncthreads();
    const float* wr = w_lin + i * 512;
    float acc = 0.f;
#pragma unroll 8
    for (int l = 0; l < 512; ++l) acc += wr[l] * lat[l];
    const float C_LIN  = 0.04419417382415922f;   // 1/sqrt(512)
    const float C_CONV = 0.014731391274719742f;  // 1/sqrt(4608)
    float s = acc * C_LIN + b_lin[i];
    g_smod[b * 512 + i] = s * C_CONV;
    g_s2[b * 512 + i]   = s * s;
}

// ---------------------------------------------------------------------------
// K2: sigma_inv[b,o]
// ---------------------------------------------------------------------------
__global__ void k_sigma(const float* __restrict__ w_conv) {
    __shared__ float red[8][128];
    const int o = blockIdx.x;
    const int tid = threadIdx.x;
    float acc[8];
#pragma unroll
    for (int b = 0; b < 8; ++b) acc[b] = 0.f;
    for (int i = tid; i < 512; i += 128) {
        const float* wp = w_conv + ((size_t)o * 512 + i) * 9;
        float ws = 0.f;
#pragma unroll
        for (int t = 0; t < 9; ++t) { float v = wp[t]; ws += v * v; }
#pragma unroll
        for (int b = 0; b < 8; ++b) acc[b] += ws * g_s2[b * 512 + i];
    }
#pragma unroll
    for (int b = 0; b < 8; ++b) red[b][tid] = acc[b];
    __syncthreads();
    for (int st = 64; st > 0; st >>= 1) {
        if (tid < st) {
#pragma unroll
            for (int b = 0; b < 8; ++b) red[b][tid] += red[b][tid + st];
        }
        __syncthreads();
    }
    if (tid < 8) {
        const float C2 = 1.0f / 4608.0f;
        g_sig[tid * 512 + o] = rsqrtf(red[tid][0] * C2 + 1e-8f);
    }
}

// ---------------------------------------------------------------------------
// K3: modulated weights -> bf16 hi/lo planes  [b][o][k]
// ---------------------------------------------------------------------------
__global__ void k_moda(const float* __restrict__ w_conv) {
    const int o = blockIdx.x, b = blockIdx.y;
    const float* wr = w_conv + (size_t)o * KTOT;
    const float* sm = g_smod + b * IC;
    __nv_bfloat16* ah = g_Ahi + ((size_t)(b * OC + o)) * KTOT;
    __nv_bfloat16* al = g_Alo + ((size_t)(b * OC + o)) * KTOT;
    for (int k = threadIdx.x; k < KTOT; k += 256) {
        float a = wr[k] * sm[k / 9];
        __nv_bfloat16 hi = __float2bfloat16(a);
        __nv_bfloat16 lo = __float2bfloat16(a - __bfloat162float(hi));
        ah[k] = hi;
        al[k] = lo;
    }
}

// ---------------------------------------------------------------------------
// K4: im2col -> bf16 hi/lo planes  [b][k][p]  (coalesced read + write)
// ---------------------------------------------------------------------------
__global__ void k_im2col(const float* __restrict__ x) {
    const int k = blockIdx.x, b = blockIdx.y;
    const int i = k / 9, t = k - i * 9;
    const int dy = t / 3 - 1, dx = t - (t / 3) * 3 - 1;
    const float* xc = x + ((size_t)(b * IC + i) << 12);
    __nv_bfloat16* bh = g_Bhi + ((size_t)b * KTOT + k) * PX;
    __nv_bfloat16* bl = g_Blo + ((size_t)b * KTOT + k) * PX;
    for (int p = threadIdx.x; p < PX; p += 256) {
        int h = (p >> 6) + dy, w = (p & 63) + dx;
        float v = ((unsigned)h < 64u && (unsigned)w < 64u) ? __ldg(xc + (h << 6) + w) : 0.f;
        __nv_bfloat16 hi = __float2bfloat16(v);
        __nv_bfloat16 lo = __float2bfloat16(v - __bfloat162float(hi));
        bh[p] = hi;
        bl[p] = lo;
    }
}

// ---------------------------------------------------------------------------
// K5: mma.sync bf16 split GEMM.  BM=128 (o) x BN=256 (p) x BK=16, 8 warps.
// Smem: A[4 stages][128][40]  (hi k0-15 | lo k16-31 | pad 8)   10,240 B/stage
//       B[4 stages][2 planes][16][264]  (k-major, pad 8)       16,896 B/stage
// ---------------------------------------------------------------------------
#define A_ST   10240
#define B_ST   16896
#define B_OFF  40960                 // 4 * A_ST
#define SMEM_TOTAL (B_OFF + 4 * B_ST)   // 108,544

__global__ void __launch_bounds__(256, 1)
k_gemm(const float* __restrict__ b_conv, float* __restrict__ out) {
    extern __shared__ char smem[];
    const uint32_t sb = (uint32_t)__cvta_generic_to_shared(smem);
    const int tid = threadIdx.x, wid = tid >> 5, lane = tid & 31;
    const int mt = blockIdx.x, nt = blockIdx.y, b = blockIdx.z;
    const int o0 = mt * 128, p0 = nt * 256;
    const int wm = (wid >> 2) * 64, wn = (wid & 3) * 64;

    // -------- cp.async source/dest mapping --------
    const int ap = tid >> 7;          // plane: 0=hi 1=lo
    const int ai = tid & 127;
    const __nv_bfloat16* asrc = (ap ? g_Alo : g_Ahi) + ((size_t)(b * OC + o0 + ai)) * KTOT;
    const uint32_t adst = sb + (uint32_t)(ai * 40 + ap * 16) * 2;
    const __nv_bfloat16* bsrc = (ap ? g_Blo : g_Bhi) + ((size_t)b * KTOT) * PX + p0;
    const uint32_t bdst = sb + B_OFF + (uint32_t)ap * 8448;

    auto issue = [&](int s) {
        const int st = s & 3;
        const __nv_bfloat16* a = asrc + s * 16;
        uint32_t ad = adst + st * A_ST;
        cp16(ad, a);
        cp16(ad + 16, a + 8);
        const __nv_bfloat16* bs = bsrc + (size_t)(s * 16) * PX;
        uint32_t bd = bdst + st * B_ST;
#pragma unroll
        for (int j = 0; j < 4; ++j) {
            int c = ai + j * 128;
            int kk = c >> 5, nch = c & 31;
            cp16(bd + (uint32_t)(kk * 264 + nch * 8) * 2, bs + (size_t)kk * PX + nch * 8);
        }
    };

    // -------- ldmatrix lane offsets --------
    const uint32_t a_lane = (uint32_t)(((lane & 15) * 40 + (lane >> 4) * 8) * 2);
    const uint32_t b_lane = (uint32_t)((((lane & 7) + ((lane >> 3) & 1) * 8) * 264 +
                                       ((lane >> 4) << 3)) * 2);

    float acc[4][8][4];
#pragma unroll
    for (int mi = 0; mi < 4; ++mi)
#pragma unroll
        for (int nf = 0; nf < 8; ++nf)
#pragma unroll
            for (int q = 0; q < 4; ++q) acc[mi][nf][q] = 0.f;

    issue(0); cp_commit();
    issue(1); cp_commit();
    issue(2); cp_commit();

#pragma unroll 1
    for (int s = 0; s < NKS; ++s) {
        __syncthreads();                    // previous stage's buffer fully consumed
        if (s + 3 < NKS) issue(s + 3);
        cp_commit();                        // empty group at tail keeps count uniform
        cp_wait3();
        __syncthreads();                    // stage s visible to all warps

        const int st = s & 3;
        const uint32_t ab = sb + st * A_ST;
        const uint32_t bb = sb + B_OFF + st * B_ST;

        uint32_t ahi[4][4], alo[4][4], bhi[4][4], blo[4][4];
#pragma unroll
        for (int mi = 0; mi < 4; ++mi) {
            uint32_t ad = ab + (uint32_t)((wm + mi * 16) * 80) + a_lane;
            ldsm4(ahi[mi], ad);
            ldsm4(alo[mi], ad + 32);
        }
#pragma unroll
        for (int n2 = 0; n2 < 4; ++n2) {
            uint32_t bd = bb + (uint32_t)((wn + n2 * 16) * 2) + b_lane;
            ldsm4t(bhi[n2], bd);
            ldsm4t(blo[n2], bd + 8448);
        }
#pragma unroll
        for (int mi = 0; mi < 4; ++mi)
#pragma unroll
            for (int nf = 0; nf < 8; ++nf) {
                const uint32_t* bh = &bhi[nf >> 1][(nf & 1) * 2];
                const uint32_t* bl = &blo[nf >> 1][(nf & 1) * 2];
                mma16816(acc[mi][nf], ahi[mi], bh);
                mma16816(acc[mi][nf], ahi[mi], bl);
                mma16816(acc[mi][nf], alo[mi], bh);
            }
    }

    // -------- epilogue: demodulate + bias, 32B-sector float2 stores --------
    const int row_l = lane >> 2, col_l = (lane & 3) * 2;
#pragma unroll
    for (int mi = 0; mi < 4; ++mi) {
        const int oa = o0 + wm + mi * 16 + row_l;
        const int ob = oa + 8;
        const float sa = g_sig[b * OC + oa], ba = b_conv[oa];
        const float sc = g_sig[b * OC + ob], bc = b_conv[ob];
        float* ra = out + (((size_t)(b * OC + oa)) << 12) + p0 + wn + col_l;
        float* rb = out + (((size_t)(b * OC + ob)) << 12) + p0 + wn + col_l;
#pragma unroll
        for (int nf = 0; nf < 8; ++nf) {
            float2 v0, v1;
            v0.x = acc[mi][nf][0] * sa + ba;
            v0.y = acc[mi][nf][1] * sa + ba;
            v1.x = acc[mi][nf][2] * sc + bc;
            v1.y = acc[mi][nf][3] * sc + bc;
            *(float2*)(ra + nf * 8) = v0;
            *(float2*)(rb + nf * 8) = v1;
        }
    }
}

// ---------------------------------------------------------------------------
extern "C" void kernel_launch(void* const* d_in, const int* in_sizes, int n_in,
                              void* d_out, int out_size) {
    const float* x      = (const float*)d_in[0];
    const float* latent = (const float*)d_in[1];
    const float* w_lin  = (const float*)d_in[2];
    const float* b_lin  = (const float*)d_in[3];
    const float* w_conv = (const float*)d_in[4];
    const float* b_conv = (const float*)d_in[5];
    float* out = (float*)d_out;

    cudaFuncSetAttribute(k_gemm, cudaFuncAttributeMaxDynamicSharedMemorySize, SMEM_TOTAL);

    k_style<<<NB, 512>>>(latent, w_lin, b_lin);
    k_sigma<<<OC, 128>>>(w_conv);
    k_moda<<<dim3(OC, NB), 256>>>(w_conv);
    k_im2col<<<dim3(KTOT, NB), 256>>>(x);
    k_gemm<<<dim3(4, 16, NB), 256, SMEM_TOTAL>>>(b_conv, out);
}

// round 4
// speedup vs baseline: 2.4242x; 1.2341x over previous
#include <cuda_runtime.h>
#include <cuda_bf16.h>
#include <cstdint>

#define NB   8
#define IC   512
#define OC   512
#define PX   4096
#define KTOT 4608
#define NKS  288           // KTOT / 16

// ---------------- scratch (device globals; no allocation) ----------------
__device__ float g_smod[NB * IC];
__device__ float g_s2[NB * IC];
__device__ float g_sig[NB * OC];
__device__ __nv_bfloat16 g_Ahi[(size_t)NB * OC * KTOT];     // [b][o][k]
__device__ __nv_bfloat16 g_Alo[(size_t)NB * OC * KTOT];
__device__ __nv_bfloat16 g_Bhi[(size_t)NB * KTOT * PX];     // [b][k][p]
__device__ __nv_bfloat16 g_Blo[(size_t)NB * KTOT * PX];

// ---------------- baseline-PTX helpers (valid on plain sm_103) ----------------
__device__ __forceinline__ void cp16(uint32_t dst, const void* src) {
    asm volatile("cp.async.cg.shared.global [%0], [%1], 16;" :: "r"(dst), "l"(src));
}
__device__ __forceinline__ void cp_commit() {
    asm volatile("cp.async.commit_group;" ::: "memory");
}
__device__ __forceinline__ void cp_wait2() {
    asm volatile("cp.async.wait_group 2;" ::: "memory");
}
__device__ __forceinline__ void ldsm4(uint32_t* r, uint32_t a) {
    asm volatile("ldmatrix.sync.aligned.m8n8.x4.shared.b16 {%0,%1,%2,%3}, [%4];"
                 : "=r"(r[0]), "=r"(r[1]), "=r"(r[2]), "=r"(r[3]) : "r"(a));
}
__device__ __forceinline__ void ldsm4t(uint32_t* r, uint32_t a) {
    asm volatile("ldmatrix.sync.aligned.m8n8.x4.trans.shared.b16 {%0,%1,%2,%3}, [%4];"
                 : "=r"(r[0]), "=r"(r[1]), "=r"(r[2]), "=r"(r[3]) : "r"(a));
}
__device__ __forceinline__ void mma16816(float* c, const uint32_t* a, const uint32_t* b) {
    asm volatile(
        "mma.sync.aligned.m16n8k16.row.col.f32.bf16.bf16.f32 "
        "{%0,%1,%2,%3},{%4,%5,%6,%7},{%8,%9},{%0,%1,%2,%3};"
        : "+f"(c[0]), "+f"(c[1]), "+f"(c[2]), "+f"(c[3])
        : "r"(a[0]), "r"(a[1]), "r"(a[2]), "r"(a[3]), "r"(b[0]), "r"(b[1]));
}

// ---------------------------------------------------------------------------
// K1: style  s[b,i] = latent.w_lin * C_LIN + b_lin   (warp per output i)
// ---------------------------------------------------------------------------
__global__ void k_style(const float* __restrict__ latent,
                        const float* __restrict__ w_lin,
                        const float* __restrict__ b_lin) {
    __shared__ float lat[512];
    const int b = blockIdx.x;
    const int tid = threadIdx.x, lane = tid & 31;
    lat[tid]       = latent[b * 512 + tid];
    lat[tid + 256] = latent[b * 512 + tid + 256];
    __syncthreads();
    const int i = blockIdx.y * 8 + (tid >> 5);
    const float4* wr = (const float4*)(w_lin + (size_t)i * 512);
    float acc = 0.f;
#pragma unroll
    for (int t = 0; t < 4; ++t) {
        float4 v = __ldg(wr + lane + t * 32);
        int j0 = (lane + t * 32) * 4;
        acc += v.x * lat[j0] + v.y * lat[j0 + 1] + v.z * lat[j0 + 2] + v.w * lat[j0 + 3];
    }
#pragma unroll
    for (int st = 16; st > 0; st >>= 1) acc += __shfl_xor_sync(0xffffffffu, acc, st);
    if (lane == 0) {
        const float C_LIN  = 0.04419417382415922f;   // 1/sqrt(512)
        const float C_CONV = 0.014731391274719742f;  // 1/sqrt(4608)
        float s = acc * C_LIN + b_lin[i];
        g_smod[b * 512 + i] = s * C_CONV;
        g_s2[b * 512 + i]   = s * s;
    }
}

// ---------------------------------------------------------------------------
// K2: sigma_inv[b,o]
// ---------------------------------------------------------------------------
__global__ void k_sigma(const float* __restrict__ w_conv) {
    __shared__ float red[8][128];
    const int o = blockIdx.x;
    const int tid = threadIdx.x;
    float acc[8];
#pragma unroll
    for (int b = 0; b < 8; ++b) acc[b] = 0.f;
    for (int i = tid; i < 512; i += 128) {
        const float* wp = w_conv + ((size_t)o * 512 + i) * 9;
        float ws = 0.f;
#pragma unroll
        for (int t = 0; t < 9; ++t) { float v = wp[t]; ws += v * v; }
#pragma unroll
        for (int b = 0; b < 8; ++b) acc[b] += ws * g_s2[b * 512 + i];
    }
#pragma unroll
    for (int b = 0; b < 8; ++b) red[b][tid] = acc[b];
    __syncthreads();
    for (int st = 64; st > 0; st >>= 1) {
        if (tid < st) {
#pragma unroll
            for (int b = 0; b < 8; ++b) red[b][tid] += red[b][tid + st];
        }
        __syncthreads();
    }
    if (tid < 8) {
        const float C2 = 1.0f / 4608.0f;
        g_sig[tid * 512 + o] = rsqrtf(red[tid][0] * C2 + 1e-8f);
    }
}

// ---------------------------------------------------------------------------
// K3: modulated weights -> bf16 hi/lo planes  [b][o][k]  (16B stores)
// ---------------------------------------------------------------------------
__global__ void k_moda(const float* __restrict__ w_conv) {
    const int o = blockIdx.x, b = blockIdx.y;
    const float* wr = w_conv + (size_t)o * KTOT;
    const float* sm = g_smod + b * IC;
    __nv_bfloat16* ah = g_Ahi + ((size_t)(b * OC + o)) * KTOT;
    __nv_bfloat16* al = g_Alo + ((size_t)(b * OC + o)) * KTOT;
    for (int g = threadIdx.x; g < KTOT / 8; g += 256) {
        const int k0 = g * 8;
        __nv_bfloat16 hv[8], lv[8];
#pragma unroll
        for (int e = 0; e < 8; ++e) {
            int k = k0 + e;
            float a = __ldg(wr + k) * sm[k / 9];
            __nv_bfloat16 hi = __float2bfloat16(a);
            hv[e] = hi;
            lv[e] = __float2bfloat16(a - __bfloat162float(hi));
        }
        *(uint4*)(ah + k0) = *(const uint4*)hv;
        *(uint4*)(al + k0) = *(const uint4*)lv;
    }
}

// ---------------------------------------------------------------------------
// K4: im2col -> bf16 hi/lo planes  [b][k][p]  (8 px/thread, 16B stores)
// ---------------------------------------------------------------------------
__global__ void k_im2col(const float* __restrict__ x) {
    const int k = blockIdx.y, b = blockIdx.z;
    const int i = k / 9, t = k - i * 9;
    const int dy = t / 3 - 1, dx = t - (t / 3) * 3 - 1;
    const float* xc = x + ((size_t)(b * IC + i) << 12);
    const int p0 = blockIdx.x * 2048 + threadIdx.x * 8;   // 8 px, same image row
    const int h = (p0 >> 6) + dy;
    const int w0 = (p0 & 63) + dx;
    __nv_bfloat16 hv[8], lv[8];
    if ((unsigned)h < 64u) {
        const float* row = xc + (h << 6);
#pragma unroll
        for (int e = 0; e < 8; ++e) {
            int w = w0 + e;
            float v = ((unsigned)w < 64u) ? __ldg(row + w) : 0.f;
            __nv_bfloat16 hi = __float2bfloat16(v);
            hv[e] = hi;
            lv[e] = __float2bfloat16(v - __bfloat162float(hi));
        }
    } else {
#pragma unroll
        for (int e = 0; e < 8; ++e) { hv[e] = __float2bfloat16(0.f); lv[e] = hv[e]; }
    }
    const size_t off = ((size_t)b * KTOT + k) * PX + p0;
    *(uint4*)(g_Bhi + off) = *(const uint4*)hv;
    *(uint4*)(g_Blo + off) = *(const uint4*)lv;
}

// ---------------------------------------------------------------------------
// K5: mma.sync bf16 split GEMM.  BM=128 x BN=256 x BK=16, 512 threads / 16 warps
// (warp tile 32x64, 4 warps per SMSP). Single __syncthreads per stage.
// Smem: A[4][128][40] (hi16|lo16|pad8)  10,240 B/stage
//       B[4][2][16][264] (k-major, pad8) 16,896 B/stage
// ---------------------------------------------------------------------------
#define A_ST   10240
#define B_ST   16896
#define B_OFF  40960
#define SMEM_TOTAL (B_OFF + 4 * B_ST)   // 108,544

__global__ void __launch_bounds__(512, 1)
k_gemm(const float* __restrict__ b_conv, float* __restrict__ out) {
    extern __shared__ char smem[];
    const uint32_t sb = (uint32_t)__cvta_generic_to_shared(smem);
    const int tid = threadIdx.x, wid = tid >> 5, lane = tid & 31;
    const int mt = blockIdx.x, nt = blockIdx.y, b = blockIdx.z;
    const int o0 = mt * 128, p0 = nt * 256;
    const int wm = (wid >> 2) * 32, wn = (wid & 3) * 64;

    // -------- A cp.async mapping: 1 cp16/thread --------
    const int arow = tid >> 2, aseg = tid & 3;        // seg: plane*2 + half
    const int apl = aseg >> 1, ahalf = aseg & 1;
    const __nv_bfloat16* asrc =
        (apl ? g_Alo : g_Ahi) + ((size_t)(b * OC + o0 + arow)) * KTOT + ahalf * 8;
    const uint32_t adst = sb + (uint32_t)(arow * 80 + apl * 32 + ahalf * 16);

    // -------- B cp.async mapping: 2 cp16/thread (hi + lo, same coords) --------
    const int bkk = tid >> 5, bnch = tid & 31;        // 16 k-rows x 32 chunks
    const __nv_bfloat16* bhsrc = g_Bhi + ((size_t)b * KTOT) * PX + p0 + bnch * 8;
    const __nv_bfloat16* blsrc = g_Blo + ((size_t)b * KTOT) * PX + p0 + bnch * 8;
    const uint32_t bdst = sb + B_OFF + (uint32_t)(bkk * 264 + bnch * 8) * 2;

    auto issue = [&](int s) {
        const int st = s & 3;
        cp16(adst + st * A_ST, asrc + s * 16);
        const size_t so = (size_t)(s * 16 + bkk) * PX;
        cp16(bdst + st * B_ST, bhsrc + so);
        cp16(bdst + st * B_ST + 8448, blsrc + so);
    };

    // -------- ldmatrix lane offsets --------
    const uint32_t a_lane = (uint32_t)((lane & 15) * 80 + (lane >> 4) * 16);
    const uint32_t b_lane = (uint32_t)((((lane & 7) + ((lane >> 3) & 1) * 8) * 264 +
                                       ((lane >> 4) << 3)) * 2);

    float acc[2][8][4];
#pragma unroll
    for (int mi = 0; mi < 2; ++mi)
#pragma unroll
        for (int j = 0; j < 8; ++j)
#pragma unroll
            for (int q = 0; q < 4; ++q) acc[mi][j][q] = 0.f;

    issue(0); cp_commit();
    issue(1); cp_commit();
    issue(2); cp_commit();

#pragma unroll 1
    for (int s = 0; s < NKS; ++s) {
        cp_wait2();
        __syncthreads();
        if (s + 3 < NKS) issue(s + 3);
        cp_commit();

        const int st = s & 3;
        const uint32_t ab = sb + st * A_ST;
        const uint32_t bb = sb + B_OFF + st * B_ST;

        uint32_t ahi[2][4], alo[2][4];
#pragma unroll
        for (int mi = 0; mi < 2; ++mi) {
            uint32_t ad = ab + (uint32_t)((wm + mi * 16) * 80) + a_lane;
            ldsm4(ahi[mi], ad);
            ldsm4(alo[mi], ad + 32);
        }
#pragma unroll
        for (int n2 = 0; n2 < 4; ++n2) {
            uint32_t bhi[4], blo[4];
            uint32_t bd = bb + (uint32_t)((wn + n2 * 16) * 2) + b_lane;
            ldsm4t(bhi, bd);
            ldsm4t(blo, bd + 8448);
#pragma unroll
            for (int mi = 0; mi < 2; ++mi)
#pragma unroll
                for (int nf = 0; nf < 2; ++nf) {
                    float* c = acc[mi][n2 * 2 + nf];
                    const uint32_t* bh = &bhi[nf * 2];
                    const uint32_t* bl = &blo[nf * 2];
                    mma16816(c, ahi[mi], bh);
                    mma16816(c, ahi[mi], bl);
                    mma16816(c, alo[mi], bh);
                }
        }
    }

    // -------- epilogue: demodulate + bias --------
    const int row_l = lane >> 2, col_l = (lane & 3) * 2;
#pragma unroll
    for (int mi = 0; mi < 2; ++mi) {
        const int oa = o0 + wm + mi * 16 + row_l;
        const int ob = oa + 8;
        const float sa = g_sig[b * OC + oa], ba = b_conv[oa];
        const float sc = g_sig[b * OC + ob], bc = b_conv[ob];
        float* ra = out + (((size_t)(b * OC + oa)) << 12) + p0 + wn + col_l;
        float* rb = out + (((size_t)(b * OC + ob)) << 12) + p0 + wn + col_l;
#pragma unroll
        for (int j = 0; j < 8; ++j) {
            float2 v0, v1;
            v0.x = acc[mi][j][0] * sa + ba;
            v0.y = acc[mi][j][1] * sa + ba;
            v1.x = acc[mi][j][2] * sc + bc;
            v1.y = acc[mi][j][3] * sc + bc;
            *(float2*)(ra + j * 8) = v0;
            *(float2*)(rb + j * 8) = v1;
        }
    }
}

// ---------------------------------------------------------------------------
extern "C" void kernel_launch(void* const* d_in, const int* in_sizes, int n_in,
                              void* d_out, int out_size) {
    const float* x      = (const float*)d_in[0];
    const float* latent = (const float*)d_in[1];
    const float* w_lin  = (const float*)d_in[2];
    const float* b_lin  = (const float*)d_in[3];
    const float* w_conv = (const float*)d_in[4];
    const float* b_conv = (const float*)d_in[5];
    float* out = (float*)d_out;

    cudaFuncSetAttribute(k_gemm, cudaFuncAttributeMaxDynamicSharedMemorySize, SMEM_TOTAL);

    k_style<<<dim3(NB, 64), 256>>>(latent, w_lin, b_lin);
    k_sigma<<<OC, 128>>>(w_conv);
    k_moda<<<dim3(OC, NB), 256>>>(w_conv);
    k_im2col<<<dim3(PX / 2048, KTOT, NB), 256>>>(x);
    k_gemm<<<dim3(4, 16, NB), 512, SMEM_TOTAL>>>(b_conv, out);
}